// round 14
// baseline (speedup 1.0000x reference)
#include <cuda_runtime.h>
#include <cuda_fp16.h>
#include <mma.h>
#include <math.h>

using namespace nvcuda;

#define NN 100000
#define EE 1000000

// Scratch (device globals — no allocation allowed)
__device__ int   g_is32;
__device__ int   g_ctr;
__device__ int   g_csr[EE];
__device__ int   g_degi[NN];
__device__ int   g_off[NN];
__device__ int   g_cur[NN];
__device__ float g_dinv[NN];
__device__ __align__(16) float  g_b1p[112];
__device__ __align__(16) float  g_b2p[64];
__device__ __align__(16) __half g_w1h[64 * 112];
__device__ __align__(16) __half g_w2h[112 * 64];
__device__ __align__(16) __half g_w3h[64 * 32];
__device__ __align__(16) __half g_hx[(size_t)NN * 64];
__device__ __align__(16) __half g_h1[(size_t)NN * 64];
__device__ __align__(16) __half g_h2[(size_t)NN * 112];

// ---------------- setup: zero deg/ctr + dtype detect + x->half ----------------
__global__ void k_setup(const float* __restrict__ x, __half* __restrict__ xh,
                        const long long* __restrict__ edge64, int E) {
    int idx = blockIdx.x * blockDim.x + threadIdx.x;
    if (idx < NN) g_degi[idx] = 0;
    if (idx < NN * 8) {
        float4 a = *(const float4*)(x + (size_t)idx * 8);
        float4 b = *(const float4*)(x + (size_t)idx * 8 + 4);
        __half2 h[4];
        h[0] = __float22half2_rn(make_float2(a.x, a.y));
        h[1] = __float22half2_rn(make_float2(a.z, a.w));
        h[2] = __float22half2_rn(make_float2(b.x, b.y));
        h[3] = __float22half2_rn(make_float2(b.z, b.w));
        *(uint4*)(xh + (size_t)idx * 8) = *(uint4*)h;
    }
    if (blockIdx.x == 0) {
        if (threadIdx.x == 0) { g_is32 = 0; g_ctr = 0; }
        __syncthreads();
        int nscan = E < 4096 ? E : 4096;
        for (int j = threadIdx.x; j < nscan; j += blockDim.x) {
            long long v = edge64[j];
            if (v < 0 || v >= NN) g_is32 = 1;  // benign race
        }
    }
}

// ---------------- helpers: load 4 indices from edge buffer ----------------
__device__ __forceinline__ void load_idx4(const void* edge, bool is32, int base,
                                          int off, int* o) {
    if (is32) {
        int4 v = *(const int4*)((const int*)edge + off + base);
        o[0] = v.x; o[1] = v.y; o[2] = v.z; o[3] = v.w;
    } else {
        const long long* p = (const long long*)edge + off + base;
        longlong2 a = *(const longlong2*)p;
        longlong2 b = *(const longlong2*)(p + 2);
        o[0] = (int)a.x; o[1] = (int)a.y; o[2] = (int)b.x; o[3] = (int)b.y;
    }
}

// ---------------- degree count: 4 edges/thread, vectorized loads ----------------
__global__ void k_count(const void* __restrict__ edge, int E) {
    int q = blockIdx.x * blockDim.x + threadIdx.x;
    int base = q * 4;
    if (base >= E) return;
    bool is32 = g_is32;
    if (base + 4 <= E) {
        int d[4];
        load_idx4(edge, is32, base, E, d);
        atomicAdd(&g_degi[d[0]], 1);
        atomicAdd(&g_degi[d[1]], 1);
        atomicAdd(&g_degi[d[2]], 1);
        atomicAdd(&g_degi[d[3]], 1);
    } else {
        for (int e = base; e < E; e++) {
            int d = is32 ? ((const int*)edge)[E + e]
                         : (int)((const long long*)edge)[E + e];
            atomicAdd(&g_degi[d], 1);
        }
    }
}

// ---------------- segment allocation (unordered CSR) + dinv ----------------
__global__ void k_alloc() {
    int i = blockIdx.x * blockDim.x + threadIdx.x;
    if (i >= NN) return;
    int d = g_degi[i];
    g_dinv[i] = rsqrtf((float)d + 1.0f);  // +1 self loop
    int off = atomicAdd(&g_ctr, d);
    g_off[i] = off;
    g_cur[i] = off;
}

// ---------------- CSR fill: 4 edges/thread, vectorized loads ----------------
__global__ void k_fill(const void* __restrict__ edge, int E) {
    int q = blockIdx.x * blockDim.x + threadIdx.x;
    int base = q * 4;
    if (base >= E) return;
    bool is32 = g_is32;
    if (base + 4 <= E) {
        int s[4], d[4];
        load_idx4(edge, is32, base, 0, s);
        load_idx4(edge, is32, base, E, d);
        int p0 = atomicAdd(&g_cur[d[0]], 1);
        int p1 = atomicAdd(&g_cur[d[1]], 1);
        int p2 = atomicAdd(&g_cur[d[2]], 1);
        int p3 = atomicAdd(&g_cur[d[3]], 1);
        g_csr[p0] = s[0];
        g_csr[p1] = s[1];
        g_csr[p2] = s[2];
        g_csr[p3] = s[3];
    } else {
        for (int e = base; e < E; e++) {
            int s, d;
            if (is32) {
                const int* p = (const int*)edge;
                s = p[e]; d = p[E + e];
            } else {
                const long long* p = (const long long*)edge;
                s = (int)p[e]; d = (int)p[E + e];
            }
            int pos = atomicAdd(&g_cur[d], 1);
            g_csr[pos] = s;
        }
    }
}

// ---------------- weight/bias pad+convert (once per launch) ----------------
__global__ void k_padw(const float* __restrict__ W1, const float* __restrict__ W2,
                       const float* __restrict__ W3, const float* __restrict__ b1,
                       const float* __restrict__ b2) {
    int i = blockIdx.x * blockDim.x + threadIdx.x;
    if (i < 64 * 112) {
        int r = i / 112, c = i - r * 112;
        g_w1h[i] = __float2half(c < 100 ? W1[r * 100 + c] : 0.0f);
    } else if (i < 64 * 112 + 112 * 64) {
        int j = i - 64 * 112;
        int r = j / 64, c = j - r * 64;
        g_w2h[j] = __float2half((r < 100 && c < 50) ? W2[r * 50 + c] : 0.0f);
    } else if (i < 64 * 112 + 112 * 64 + 64 * 32) {
        int j = i - 64 * 112 - 112 * 64;
        int r = j / 32, c = j - r * 32;
        g_w3h[j] = __float2half((r < 50 && c < 25) ? W3[r * 25 + c] : 0.0f);
    }
    if (i < 112) g_b1p[i] = (i < 100) ? b1[i] : 0.0f;
    if (i < 64)  g_b2p[i] = (i < 50)  ? b2[i] : 0.0f;
}

__device__ __forceinline__ void fma_half8(float* acc, uint4 raw, float w) {
    const __half2* hp = (const __half2*)&raw;
#pragma unroll
    for (int j = 0; j < 4; j++) {
        float2 f = __half22float2(hp[j]);
        acc[2 * j]     = fmaf(f.x, w, acc[2 * j]);
        acc[2 * j + 1] = fmaf(f.y, w, acc[2 * j + 1]);
    }
}

// ---------------- gather aggregation (half payload, fp32 accum, half out) ----------------
template <int C, int LD, bool BR>
__global__ void k_aggh(const __half* __restrict__ xh, __half* __restrict__ outh,
                       const float* __restrict__ bias) {
    int idx = blockIdx.x * blockDim.x + threadIdx.x;
    if (idx >= NN * C) return;
    int i = idx / C;
    int c = idx - i * C;
    float di = g_dinv[i];
    float s2 = di * di;
    float acc[8];
    {
        uint4 raw = *(const uint4*)(xh + (size_t)i * LD + c * 8);
        const __half2* hp = (const __half2*)&raw;
#pragma unroll
        for (int j = 0; j < 4; j++) {
            float2 f = __half22float2(hp[j]);
            acc[2 * j]     = f.x * s2;
            acc[2 * j + 1] = f.y * s2;
        }
    }
    int b = g_off[i];
    int e = b + g_degi[i];
    int t = b;
    for (; t + 2 <= e; t += 2) {
        int s0 = g_csr[t];
        int s1 = g_csr[t + 1];
        float w0 = g_dinv[s0] * di;
        float w1 = g_dinv[s1] * di;
        uint4 r0 = *(const uint4*)(xh + (size_t)s0 * LD + c * 8);
        uint4 r1 = *(const uint4*)(xh + (size_t)s1 * LD + c * 8);
        fma_half8(acc, r0, w0);
        fma_half8(acc, r1, w1);
    }
    if (t < e) {
        int s0 = g_csr[t];
        float w0 = g_dinv[s0] * di;
        uint4 r0 = *(const uint4*)(xh + (size_t)s0 * LD + c * 8);
        fma_half8(acc, r0, w0);
    }
    if (BR) {
#pragma unroll
        for (int j = 0; j < 8; j++)
            acc[j] = fmaxf(acc[j] + bias[c * 8 + j], 0.0f);
    }
    __half2 h[4];
#pragma unroll
    for (int j = 0; j < 4; j++)
        h[j] = __float22half2_rn(make_float2(acc[2 * j], acc[2 * j + 1]));
    *(uint4*)(outh + (size_t)i * LD + c * 8) = *(uint4*)h;
}

// ---------------- wmma GEMM v2: padded smem (conflict-free) + RT row tiles ----------------
template <int KP, int NP, int RT, bool BR>
__global__ void k_gemm_wmma(const __half* __restrict__ X, const __half* __restrict__ W,
                            const float* __restrict__ bias, __half* __restrict__ Yh, int n) {
    constexpr int WARPS = 4;
    constexpr int ROWS = WARPS * RT * 16;
    constexpr int NT = NP / 16, KT = KP / 16;
    constexpr int XSP = KP + 8;     // padded X stride (halves)
    constexpr int NPP = NP + 8;     // padded W stride (halves)
    constexpr int SM_AB = ROWS * XSP * 2 + KP * NPP * 2;
    constexpr int SM_ST = WARPS * 16 * NP * 4;
    constexpr int SM = SM_AB > SM_ST ? SM_AB : SM_ST;
    __shared__ __align__(16) char sm[SM];
    __half* Xs = (__half*)sm;
    __half* Ws = (__half*)(sm + ROWS * XSP * 2);

    int tid = threadIdx.x;
    int wid = tid >> 5;
    int lane = tid & 31;
    int base = blockIdx.x * ROWS;

    for (int i = tid; i < KP * (NP / 8); i += blockDim.x) {
        int r = i / (NP / 8), g = i - r * (NP / 8);
        *(uint4*)(Ws + r * NPP + g * 8) = ((const uint4*)(W + r * NP))[g];
    }
    for (int i = tid; i < ROWS * (KP / 8); i += blockDim.x) {
        int r = i / (KP / 8), g = i - r * (KP / 8);
        uint4 v = {0, 0, 0, 0};
        if (base + r < n) v = ((const uint4*)(X + (size_t)(base + r) * KP))[g];
        *(uint4*)(Xs + r * XSP + g * 8) = v;
    }
    __syncthreads();

    wmma::fragment<wmma::accumulator, 16, 16, 16, float> cf[RT][NT];
#pragma unroll
    for (int rt = 0; rt < RT; rt++)
#pragma unroll
        for (int nt = 0; nt < NT; nt++) wmma::fill_fragment(cf[rt][nt], 0.0f);

    int wr = wid * RT * 16;
#pragma unroll
    for (int kt = 0; kt < KT; kt++) {
        wmma::fragment<wmma::matrix_a, 16, 16, 16, __half, wmma::row_major> af[RT];
#pragma unroll
        for (int rt = 0; rt < RT; rt++)
            wmma::load_matrix_sync(af[rt], Xs + (wr + rt * 16) * XSP + kt * 16, XSP);
#pragma unroll
        for (int nt = 0; nt < NT; nt++) {
            wmma::fragment<wmma::matrix_b, 16, 16, 16, __half, wmma::row_major> bf;
            wmma::load_matrix_sync(bf, Ws + kt * 16 * NPP + nt * 16, NPP);
#pragma unroll
            for (int rt = 0; rt < RT; rt++)
                wmma::mma_sync(cf[rt][nt], af[rt], bf, cf[rt][nt]);
        }
    }
    __syncthreads();  // done with Xs/Ws; alias per-warp staging over sm

    float* stg = (float*)sm + wid * 16 * NP;
#pragma unroll
    for (int rt = 0; rt < RT; rt++) {
#pragma unroll
        for (int nt = 0; nt < NT; nt++)
            wmma::store_matrix_sync(stg + nt * 16, cf[rt][nt], NP, wmma::mem_row_major);
        __syncwarp();
        int rbase = base + wr + rt * 16;
        for (int i = lane; i < 16 * (NP / 4); i += 32) {
            int r = i / (NP / 4), c = i - r * (NP / 4);
            if (rbase + r < n) {
                float4 v = *(const float4*)(stg + r * NP + c * 4);
                if (BR) {
                    float4 bb = *(const float4*)(bias + c * 4);
                    v.x = fmaxf(v.x + bb.x, 0.0f); v.y = fmaxf(v.y + bb.y, 0.0f);
                    v.z = fmaxf(v.z + bb.z, 0.0f); v.w = fmaxf(v.w + bb.w, 0.0f);
                }
                __half2 h01 = __float22half2_rn(make_float2(v.x, v.y));
                __half2 h23 = __float22half2_rn(make_float2(v.z, v.w));
                uint2 pk = {*(unsigned*)&h01, *(unsigned*)&h23};
                *(uint2*)(Yh + (size_t)(rbase + r) * NP + c * 4) = pk;
            }
        }
        __syncwarp();
    }
}

// ---------------- fused agg3 + epilogue MLP: one thread per node ----------------
__global__ void k_agg3_final(const __half* __restrict__ xh, const float* __restrict__ b3,
                             const float* __restrict__ Wl1, const float* __restrict__ bl1,
                             const float* __restrict__ Wl2, const float* __restrict__ bl2,
                             const float* __restrict__ Wl3, const float* __restrict__ bl3,
                             float* __restrict__ out, int n) {
    __shared__ float sW1[25 * 25], sW2[25 * 10], sW3[10];
    __shared__ float sb3[25], sb1[25], sb2[10], sb3l;
    for (int i = threadIdx.x; i < 25 * 25; i += blockDim.x) sW1[i] = Wl1[i];
    for (int i = threadIdx.x; i < 25 * 10; i += blockDim.x) sW2[i] = Wl2[i];
    if (threadIdx.x < 10) sW3[threadIdx.x] = Wl3[threadIdx.x];
    if (threadIdx.x < 25) { sb3[threadIdx.x] = b3[threadIdx.x]; sb1[threadIdx.x] = bl1[threadIdx.x]; }
    if (threadIdx.x < 10) sb2[threadIdx.x] = bl2[threadIdx.x];
    if (threadIdx.x == 0) sb3l = bl3[0];
    __syncthreads();

    int i = blockIdx.x * blockDim.x + threadIdx.x;
    if (i >= n) return;

    float di = g_dinv[i];
    float s2 = di * di;
    float acc[32];
    {
        const uint4* p = (const uint4*)(xh + (size_t)i * 32);
#pragma unroll
        for (int q = 0; q < 4; q++) {
            uint4 raw = p[q];
            const __half2* hp = (const __half2*)&raw;
#pragma unroll
            for (int j = 0; j < 4; j++) {
                float2 f = __half22float2(hp[j]);
                acc[q * 8 + 2 * j]     = f.x * s2;
                acc[q * 8 + 2 * j + 1] = f.y * s2;
            }
        }
    }
    int b = g_off[i];
    int e = b + g_degi[i];
    for (int t = b; t < e; t++) {
        int s = g_csr[t];
        float w = g_dinv[s] * di;
        const uint4* p = (const uint4*)(xh + (size_t)s * 32);
        uint4 r0 = p[0], r1 = p[1], r2 = p[2], r3 = p[3];
        fma_half8(acc,      r0, w);
        fma_half8(acc + 8,  r1, w);
        fma_half8(acc + 16, r2, w);
        fma_half8(acc + 24, r3, w);
    }

    float v[25];
#pragma unroll
    for (int f = 0; f < 25; f++)
        v[f] = fmaxf(acc[f] + sb3[f], 0.0f);

    float h1[25];
#pragma unroll
    for (int c = 0; c < 25; c++) {
        float a = sb1[c];
#pragma unroll
        for (int k = 0; k < 25; k++) a = fmaf(v[k], sW1[k * 25 + c], a);
        h1[c] = fmaxf(a, 0.0f);
    }
    float h2[10];
#pragma unroll
    for (int c = 0; c < 10; c++) {
        float a = sb2[c];
#pragma unroll
        for (int k = 0; k < 25; k++) a = fmaf(h1[k], sW2[k * 10 + c], a);
        h2[c] = fmaxf(a, 0.0f);
    }
    float o = sb3l;
#pragma unroll
    for (int k = 0; k < 10; k++) o = fmaf(h2[k], sW3[k], o);
    out[i] = fmaxf(o, 0.0f);
}

// ---------------- launch ----------------
extern "C" void kernel_launch(void* const* d_in, const int* in_sizes, int n_in,
                              void* d_out, int out_size) {
    const float* x   = (const float*)d_in[0];
    const float* W1  = (const float*)d_in[1];
    const float* b1  = (const float*)d_in[2];
    const float* W2  = (const float*)d_in[3];
    const float* b2  = (const float*)d_in[4];
    const float* W3  = (const float*)d_in[5];
    const float* b3  = (const float*)d_in[6];
    const float* Wl1 = (const float*)d_in[7];
    const float* bl1 = (const float*)d_in[8];
    const float* Wl2 = (const float*)d_in[9];
    const float* bl2 = (const float*)d_in[10];
    const float* Wl3 = (const float*)d_in[11];
    const float* bl3 = (const float*)d_in[12];
    const void* edge = d_in[13];
    int E = in_sizes[13] / 2;

    float *b1p, *b2p;
    __half *HX, *H1, *H2, *W1H, *W2H, *W3H;
    cudaGetSymbolAddress((void**)&b1p, g_b1p);
    cudaGetSymbolAddress((void**)&b2p, g_b2p);
    cudaGetSymbolAddress((void**)&HX,  g_hx);
    cudaGetSymbolAddress((void**)&H1,  g_h1);
    cudaGetSymbolAddress((void**)&H2,  g_h2);
    cudaGetSymbolAddress((void**)&W1H, g_w1h);
    cudaGetSymbolAddress((void**)&W2H, g_w2h);
    cudaGetSymbolAddress((void**)&W3H, g_w3h);

    const int T = 256;
    int gN = (NN + T - 1) / T;
    int gE4 = ((E + 3) / 4 + T - 1) / T;

    // setup + unordered-CSR build (vectorized edge passes)
    k_setup<<<(NN * 8 + T - 1) / T, T>>>(x, HX, (const long long*)edge, E);
    k_count<<<gE4, T>>>(edge, E);
    k_alloc<<<gN, T>>>();
    k_fill<<<gE4, T>>>(edge, E);
    k_padw<<<64, T>>>(W1, W2, W3, b1, b2);

    // ----- Layer 1: agg (64) -> half; wmma 64->112 (+b1,relu), RT=1 -----
    k_aggh<8, 64, false><<<NN * 8 / T, T>>>(HX, H1, nullptr);
    k_gemm_wmma<64, 112, 1, true><<<(NN + 63) / 64, 128>>>(H1, W1H, b1p, H2, NN);

    // ----- Layer 2: wmma 112->64 raw, RT=2; agg (64) +b2,relu -----
    k_gemm_wmma<112, 64, 2, false><<<(NN + 127) / 128, 128>>>(H2, W2H, nullptr, HX, NN);
    k_aggh<8, 64, true><<<NN * 8 / T, T>>>(HX, H1, b2p);

    // ----- Layer 3: wmma 64->32 raw, RT=2; fused agg (32) + MLP epilogue -----
    k_gemm_wmma<64, 32, 2, false><<<(NN + 127) / 128, 128>>>(H1, W3H, nullptr, H2, NN);
    k_agg3_final<<<gN, T>>>(H2, b3, Wl1, bl1, Wl2, bl2, Wl3, bl3, (float*)d_out, NN);
}

// round 15
// speedup vs baseline: 1.0266x; 1.0266x over previous
#include <cuda_runtime.h>
#include <cuda_fp16.h>
#include <mma.h>
#include <math.h>

using namespace nvcuda;

#define NN 100000
#define EE 1000000

// Scratch (device globals — no allocation allowed)
__device__ int   g_is32;
__device__ int   g_ctr;
__device__ __align__(8) int2 g_csrw[EE];   // {src, float-bits dinv[src]}
__device__ int   g_degi[NN];
__device__ int   g_off[NN];
__device__ int   g_cur[NN];
__device__ float g_dinv[NN];
__device__ __align__(16) float  g_b1p[112];
__device__ __align__(16) float  g_b2p[64];
__device__ __align__(16) __half g_w1h[64 * 112];
__device__ __align__(16) __half g_w2h[112 * 64];
__device__ __align__(16) __half g_w3h[64 * 32];
__device__ __align__(16) __half g_hx[(size_t)NN * 64];
__device__ __align__(16) __half g_h1[(size_t)NN * 64];
__device__ __align__(16) __half g_h2[(size_t)NN * 112];

// ---------------- setup: zero deg/ctr + dtype detect + x->half ----------------
__global__ void k_setup(const float* __restrict__ x, __half* __restrict__ xh,
                        const long long* __restrict__ edge64, int E) {
    int idx = blockIdx.x * blockDim.x + threadIdx.x;
    if (idx < NN) g_degi[idx] = 0;
    if (idx < NN * 8) {
        float4 a = *(const float4*)(x + (size_t)idx * 8);
        float4 b = *(const float4*)(x + (size_t)idx * 8 + 4);
        __half2 h[4];
        h[0] = __float22half2_rn(make_float2(a.x, a.y));
        h[1] = __float22half2_rn(make_float2(a.z, a.w));
        h[2] = __float22half2_rn(make_float2(b.x, b.y));
        h[3] = __float22half2_rn(make_float2(b.z, b.w));
        *(uint4*)(xh + (size_t)idx * 8) = *(uint4*)h;
    }
    if (blockIdx.x == 0) {
        if (threadIdx.x == 0) { g_is32 = 0; g_ctr = 0; }
        __syncthreads();
        int nscan = E < 4096 ? E : 4096;
        for (int j = threadIdx.x; j < nscan; j += blockDim.x) {
            long long v = edge64[j];
            if (v < 0 || v >= NN) g_is32 = 1;  // benign race
        }
    }
}

// ---------------- degree count (1 edge/thread — R13 config) ----------------
__global__ void k_count(const void* __restrict__ edge, int E) {
    int e = blockIdx.x * blockDim.x + threadIdx.x;
    if (e >= E) return;
    int d = g_is32 ? ((const int*)edge)[E + e]
                   : (int)((const long long*)edge)[E + e];
    atomicAdd(&g_degi[d], 1);
}

// ---------------- segment alloc + dinv + weight/bias pad (merged) ----------------
__global__ void k_alloc_padw(const float* __restrict__ W1, const float* __restrict__ W2,
                             const float* __restrict__ W3, const float* __restrict__ b1,
                             const float* __restrict__ b2) {
    int i = blockIdx.x * blockDim.x + threadIdx.x;
    if (i < NN) {
        int d = g_degi[i];
        g_dinv[i] = rsqrtf((float)d + 1.0f);  // +1 self loop
        int off = atomicAdd(&g_ctr, d);
        g_off[i] = off;
        g_cur[i] = off;
    }
    if (i < 64 * 112) {
        int r = i / 112, c = i - r * 112;
        g_w1h[i] = __float2half(c < 100 ? W1[r * 100 + c] : 0.0f);
    }
    if (i < 112 * 64) {
        int r = i / 64, c = i - r * 64;
        g_w2h[i] = __float2half((r < 100 && c < 50) ? W2[r * 50 + c] : 0.0f);
    }
    if (i < 64 * 32) {
        int r = i / 32, c = i - r * 32;
        g_w3h[i] = __float2half((r < 50 && c < 25) ? W3[r * 25 + c] : 0.0f);
    }
    if (i < 112) g_b1p[i] = (i < 100) ? b1[i] : 0.0f;
    if (i < 64)  g_b2p[i] = (i < 50)  ? b2[i] : 0.0f;
}

// ---------------- CSR fill: store {src, dinv[src]} pairs ----------------
__global__ void k_fill(const void* __restrict__ edge, int E) {
    int e = blockIdx.x * blockDim.x + threadIdx.x;
    if (e >= E) return;
    int s, d;
    if (g_is32) {
        const int* p = (const int*)edge;
        s = p[e]; d = p[E + e];
    } else {
        const long long* p = (const long long*)edge;
        s = (int)p[e]; d = (int)p[E + e];
    }
    float ds = g_dinv[s];
    int pos = atomicAdd(&g_cur[d], 1);
    g_csrw[pos] = make_int2(s, __float_as_int(ds));
}

__device__ __forceinline__ void fma_half8(float* acc, uint4 raw, float w) {
    const __half2* hp = (const __half2*)&raw;
#pragma unroll
    for (int j = 0; j < 4; j++) {
        float2 f = __half22float2(hp[j]);
        acc[2 * j]     = fmaf(f.x, w, acc[2 * j]);
        acc[2 * j + 1] = fmaf(f.y, w, acc[2 * j + 1]);
    }
}

// ---------------- gather aggregation (2-deep chain: csrw -> xh) ----------------
template <int C, int LD, bool BR>
__global__ void k_aggh(const __half* __restrict__ xh, __half* __restrict__ outh,
                       const float* __restrict__ bias) {
    int idx = blockIdx.x * blockDim.x + threadIdx.x;
    if (idx >= NN * C) return;
    int i = idx / C;
    int c = idx - i * C;
    float di = g_dinv[i];
    float s2 = di * di;
    float acc[8];
    {
        uint4 raw = *(const uint4*)(xh + (size_t)i * LD + c * 8);
        const __half2* hp = (const __half2*)&raw;
#pragma unroll
        for (int j = 0; j < 4; j++) {
            float2 f = __half22float2(hp[j]);
            acc[2 * j]     = f.x * s2;
            acc[2 * j + 1] = f.y * s2;
        }
    }
    int b = g_off[i];
    int e = b + g_degi[i];
    int t = b;
    for (; t + 2 <= e; t += 2) {
        int2 sw0 = g_csrw[t];
        int2 sw1 = g_csrw[t + 1];
        float w0 = __int_as_float(sw0.y) * di;
        float w1 = __int_as_float(sw1.y) * di;
        uint4 r0 = *(const uint4*)(xh + (size_t)sw0.x * LD + c * 8);
        uint4 r1 = *(const uint4*)(xh + (size_t)sw1.x * LD + c * 8);
        fma_half8(acc, r0, w0);
        fma_half8(acc, r1, w1);
    }
    if (t < e) {
        int2 sw0 = g_csrw[t];
        float w0 = __int_as_float(sw0.y) * di;
        uint4 r0 = *(const uint4*)(xh + (size_t)sw0.x * LD + c * 8);
        fma_half8(acc, r0, w0);
    }
    if (BR) {
#pragma unroll
        for (int j = 0; j < 8; j++)
            acc[j] = fmaxf(acc[j] + bias[c * 8 + j], 0.0f);
    }
    __half2 h[4];
#pragma unroll
    for (int j = 0; j < 4; j++)
        h[j] = __float22half2_rn(make_float2(acc[2 * j], acc[2 * j + 1]));
    *(uint4*)(outh + (size_t)i * LD + c * 8) = *(uint4*)h;
}

// ---------------- wmma GEMM v2: padded smem (conflict-free) + RT row tiles ----------------
template <int KP, int NP, int RT, bool BR>
__global__ void k_gemm_wmma(const __half* __restrict__ X, const __half* __restrict__ W,
                            const float* __restrict__ bias, __half* __restrict__ Yh, int n) {
    constexpr int WARPS = 4;
    constexpr int ROWS = WARPS * RT * 16;
    constexpr int NT = NP / 16, KT = KP / 16;
    constexpr int XSP = KP + 8;     // padded X stride (halves)
    constexpr int NPP = NP + 8;     // padded W stride (halves)
    constexpr int SM_AB = ROWS * XSP * 2 + KP * NPP * 2;
    constexpr int SM_ST = WARPS * 16 * NP * 4;
    constexpr int SM = SM_AB > SM_ST ? SM_AB : SM_ST;
    __shared__ __align__(16) char sm[SM];
    __half* Xs = (__half*)sm;
    __half* Ws = (__half*)(sm + ROWS * XSP * 2);

    int tid = threadIdx.x;
    int wid = tid >> 5;
    int lane = tid & 31;
    int base = blockIdx.x * ROWS;

    for (int i = tid; i < KP * (NP / 8); i += blockDim.x) {
        int r = i / (NP / 8), g = i - r * (NP / 8);
        *(uint4*)(Ws + r * NPP + g * 8) = ((const uint4*)(W + r * NP))[g];
    }
    for (int i = tid; i < ROWS * (KP / 8); i += blockDim.x) {
        int r = i / (KP / 8), g = i - r * (KP / 8);
        uint4 v = {0, 0, 0, 0};
        if (base + r < n) v = ((const uint4*)(X + (size_t)(base + r) * KP))[g];
        *(uint4*)(Xs + r * XSP + g * 8) = v;
    }
    __syncthreads();

    wmma::fragment<wmma::accumulator, 16, 16, 16, float> cf[RT][NT];
#pragma unroll
    for (int rt = 0; rt < RT; rt++)
#pragma unroll
        for (int nt = 0; nt < NT; nt++) wmma::fill_fragment(cf[rt][nt], 0.0f);

    int wr = wid * RT * 16;
#pragma unroll
    for (int kt = 0; kt < KT; kt++) {
        wmma::fragment<wmma::matrix_a, 16, 16, 16, __half, wmma::row_major> af[RT];
#pragma unroll
        for (int rt = 0; rt < RT; rt++)
            wmma::load_matrix_sync(af[rt], Xs + (wr + rt * 16) * XSP + kt * 16, XSP);
#pragma unroll
        for (int nt = 0; nt < NT; nt++) {
            wmma::fragment<wmma::matrix_b, 16, 16, 16, __half, wmma::row_major> bf;
            wmma::load_matrix_sync(bf, Ws + kt * 16 * NPP + nt * 16, NPP);
#pragma unroll
            for (int rt = 0; rt < RT; rt++)
                wmma::mma_sync(cf[rt][nt], af[rt], bf, cf[rt][nt]);
        }
    }
    __syncthreads();  // done with Xs/Ws; alias per-warp staging over sm

    float* stg = (float*)sm + wid * 16 * NP;
#pragma unroll
    for (int rt = 0; rt < RT; rt++) {
#pragma unroll
        for (int nt = 0; nt < NT; nt++)
            wmma::store_matrix_sync(stg + nt * 16, cf[rt][nt], NP, wmma::mem_row_major);
        __syncwarp();
        int rbase = base + wr + rt * 16;
        for (int i = lane; i < 16 * (NP / 4); i += 32) {
            int r = i / (NP / 4), c = i - r * (NP / 4);
            if (rbase + r < n) {
                float4 v = *(const float4*)(stg + r * NP + c * 4);
                if (BR) {
                    float4 bb = *(const float4*)(bias + c * 4);
                    v.x = fmaxf(v.x + bb.x, 0.0f); v.y = fmaxf(v.y + bb.y, 0.0f);
                    v.z = fmaxf(v.z + bb.z, 0.0f); v.w = fmaxf(v.w + bb.w, 0.0f);
                }
                __half2 h01 = __float22half2_rn(make_float2(v.x, v.y));
                __half2 h23 = __float22half2_rn(make_float2(v.z, v.w));
                uint2 pk = {*(unsigned*)&h01, *(unsigned*)&h23};
                *(uint2*)(Yh + (size_t)(rbase + r) * NP + c * 4) = pk;
            }
        }
        __syncwarp();
    }
}

// ---------------- fused agg3 + epilogue MLP: one thread per node ----------------
__global__ void k_agg3_final(const __half* __restrict__ xh, const float* __restrict__ b3,
                             const float* __restrict__ Wl1, const float* __restrict__ bl1,
                             const float* __restrict__ Wl2, const float* __restrict__ bl2,
                             const float* __restrict__ Wl3, const float* __restrict__ bl3,
                             float* __restrict__ out, int n) {
    __shared__ float sW1[25 * 25], sW2[25 * 10], sW3[10];
    __shared__ float sb3[25], sb1[25], sb2[10], sb3l;
    for (int i = threadIdx.x; i < 25 * 25; i += blockDim.x) sW1[i] = Wl1[i];
    for (int i = threadIdx.x; i < 25 * 10; i += blockDim.x) sW2[i] = Wl2[i];
    if (threadIdx.x < 10) sW3[threadIdx.x] = Wl3[threadIdx.x];
    if (threadIdx.x < 25) { sb3[threadIdx.x] = b3[threadIdx.x]; sb1[threadIdx.x] = bl1[threadIdx.x]; }
    if (threadIdx.x < 10) sb2[threadIdx.x] = bl2[threadIdx.x];
    if (threadIdx.x == 0) sb3l = bl3[0];
    __syncthreads();

    int i = blockIdx.x * blockDim.x + threadIdx.x;
    if (i >= n) return;

    float di = g_dinv[i];
    float s2 = di * di;
    float acc[32];
    {
        const uint4* p = (const uint4*)(xh + (size_t)i * 32);
#pragma unroll
        for (int q = 0; q < 4; q++) {
            uint4 raw = p[q];
            const __half2* hp = (const __half2*)&raw;
#pragma unroll
            for (int j = 0; j < 4; j++) {
                float2 f = __half22float2(hp[j]);
                acc[q * 8 + 2 * j]     = f.x * s2;
                acc[q * 8 + 2 * j + 1] = f.y * s2;
            }
        }
    }
    int b = g_off[i];
    int e = b + g_degi[i];
    for (int t = b; t < e; t++) {
        int2 sw = g_csrw[t];
        float w = __int_as_float(sw.y) * di;
        const uint4* p = (const uint4*)(xh + (size_t)sw.x * 32);
        uint4 r0 = p[0], r1 = p[1], r2 = p[2], r3 = p[3];
        fma_half8(acc,      r0, w);
        fma_half8(acc + 8,  r1, w);
        fma_half8(acc + 16, r2, w);
        fma_half8(acc + 24, r3, w);
    }

    float v[25];
#pragma unroll
    for (int f = 0; f < 25; f++)
        v[f] = fmaxf(acc[f] + sb3[f], 0.0f);

    float h1[25];
#pragma unroll
    for (int c = 0; c < 25; c++) {
        float a = sb1[c];
#pragma unroll
        for (int k = 0; k < 25; k++) a = fmaf(v[k], sW1[k * 25 + c], a);
        h1[c] = fmaxf(a, 0.0f);
    }
    float h2[10];
#pragma unroll
    for (int c = 0; c < 10; c++) {
        float a = sb2[c];
#pragma unroll
        for (int k = 0; k < 25; k++) a = fmaf(h1[k], sW2[k * 10 + c], a);
        h2[c] = fmaxf(a, 0.0f);
    }
    float o = sb3l;
#pragma unroll
    for (int k = 0; k < 10; k++) o = fmaf(h2[k], sW3[k], o);
    out[i] = fmaxf(o, 0.0f);
}

// ---------------- launch ----------------
extern "C" void kernel_launch(void* const* d_in, const int* in_sizes, int n_in,
                              void* d_out, int out_size) {
    const float* x   = (const float*)d_in[0];
    const float* W1  = (const float*)d_in[1];
    const float* b1  = (const float*)d_in[2];
    const float* W2  = (const float*)d_in[3];
    const float* b2  = (const float*)d_in[4];
    const float* W3  = (const float*)d_in[5];
    const float* b3  = (const float*)d_in[6];
    const float* Wl1 = (const float*)d_in[7];
    const float* bl1 = (const float*)d_in[8];
    const float* Wl2 = (const float*)d_in[9];
    const float* bl2 = (const float*)d_in[10];
    const float* Wl3 = (const float*)d_in[11];
    const float* bl3 = (const float*)d_in[12];
    const void* edge = d_in[13];
    int E = in_sizes[13] / 2;

    float *b1p, *b2p;
    __half *HX, *H1, *H2, *W1H, *W2H, *W3H;
    cudaGetSymbolAddress((void**)&b1p, g_b1p);
    cudaGetSymbolAddress((void**)&b2p, g_b2p);
    cudaGetSymbolAddress((void**)&HX,  g_hx);
    cudaGetSymbolAddress((void**)&H1,  g_h1);
    cudaGetSymbolAddress((void**)&H2,  g_h2);
    cudaGetSymbolAddress((void**)&W1H, g_w1h);
    cudaGetSymbolAddress((void**)&W2H, g_w2h);
    cudaGetSymbolAddress((void**)&W3H, g_w3h);

    const int T = 256;
    int gN = (NN + T - 1) / T;
    int gE = (E + T - 1) / T;

    // setup + unordered-CSR build (1 edge/thread — R13 config; payload widened)
    k_setup<<<(NN * 8 + T - 1) / T, T>>>(x, HX, (const long long*)edge, E);
    k_count<<<gE, T>>>(edge, E);
    k_alloc_padw<<<gN, T>>>(W1, W2, W3, b1, b2);
    k_fill<<<gE, T>>>(edge, E);

    // ----- Layer 1: agg (64) -> half; wmma 64->112 (+b1,relu), RT=1 -----
    k_aggh<8, 64, false><<<NN * 8 / T, T>>>(HX, H1, nullptr);
    k_gemm_wmma<64, 112, 1, true><<<(NN + 63) / 64, 128>>>(H1, W1H, b1p, H2, NN);

    // ----- Layer 2: wmma 112->64 raw, RT=2; agg (64) +b2,relu -----
    k_gemm_wmma<112, 64, 2, false><<<(NN + 127) / 128, 128>>>(H2, W2H, nullptr, HX, NN);
    k_aggh<8, 64, true><<<NN * 8 / T, T>>>(HX, H1, b2p);

    // ----- Layer 3: wmma 64->32 raw, RT=2; fused agg (32) + MLP epilogue -----
    k_gemm_wmma<64, 32, 2, false><<<(NN + 127) / 128, 128>>>(H1, W3H, nullptr, H2, NN);
    k_agg3_final<<<gN, T>>>(H2, b3, Wl1, bl1, Wl2, bl2, Wl3, bl3, (float*)d_out, NN);
}

// round 16
// speedup vs baseline: 1.0280x; 1.0013x over previous
#include <cuda_runtime.h>
#include <cuda_fp16.h>
#include <mma.h>
#include <math.h>

using namespace nvcuda;

#define NN 100000
#define EE 1000000

// Scratch (device globals — no allocation allowed)
__device__ int   g_is32;
__device__ int   g_ctr;
__device__ __align__(8) int2 g_csrw[EE];   // {src, float-bits dinv[src]}
__device__ int   g_degi[NN];
__device__ int   g_off[NN];
__device__ int   g_cur[NN];
__device__ float g_dinv[NN];
__device__ __align__(16) float  g_b1p[112];
__device__ __align__(16) float  g_b2p[64];
__device__ __align__(16) __half g_w1h[64 * 112];
__device__ __align__(16) __half g_w2h[112 * 64];
__device__ __align__(16) __half g_w3h[64 * 32];
__device__ __align__(16) __half g_hx[(size_t)NN * 64];
__device__ __align__(16) __half g_h1[(size_t)NN * 64];
__device__ __align__(16) __half g_h2[(size_t)NN * 112];

// ---------------- setup: zero deg/ctr + dtype detect + x->half ----------------
__global__ void k_setup(const float* __restrict__ x, __half* __restrict__ xh,
                        const long long* __restrict__ edge64, int E) {
    int idx = blockIdx.x * blockDim.x + threadIdx.x;
    if (idx < NN) g_degi[idx] = 0;
    if (idx < NN * 8) {
        float4 a = *(const float4*)(x + (size_t)idx * 8);
        float4 b = *(const float4*)(x + (size_t)idx * 8 + 4);
        __half2 h[4];
        h[0] = __float22half2_rn(make_float2(a.x, a.y));
        h[1] = __float22half2_rn(make_float2(a.z, a.w));
        h[2] = __float22half2_rn(make_float2(b.x, b.y));
        h[3] = __float22half2_rn(make_float2(b.z, b.w));
        *(uint4*)(xh + (size_t)idx * 8) = *(uint4*)h;
    }
    if (blockIdx.x == 0) {
        if (threadIdx.x == 0) { g_is32 = 0; g_ctr = 0; }
        __syncthreads();
        int nscan = E < 4096 ? E : 4096;
        for (int j = threadIdx.x; j < nscan; j += blockDim.x) {
            long long v = edge64[j];
            if (v < 0 || v >= NN) g_is32 = 1;  // benign race
        }
    }
}

// ---------------- degree count ----------------
__global__ void k_count(const void* __restrict__ edge, int E) {
    int e = blockIdx.x * blockDim.x + threadIdx.x;
    if (e >= E) return;
    int d = g_is32 ? ((const int*)edge)[E + e]
                   : (int)((const long long*)edge)[E + e];
    atomicAdd(&g_degi[d], 1);
}

// ---------------- segment alloc + dinv + weight/bias pad (merged) ----------------
__global__ void k_alloc_padw(const float* __restrict__ W1, const float* __restrict__ W2,
                             const float* __restrict__ W3, const float* __restrict__ b1,
                             const float* __restrict__ b2) {
    int i = blockIdx.x * blockDim.x + threadIdx.x;
    if (i < NN) {
        int d = g_degi[i];
        g_dinv[i] = rsqrtf((float)d + 1.0f);  // +1 self loop
        int off = atomicAdd(&g_ctr, d);
        g_off[i] = off;
        g_cur[i] = off;
    }
    if (i < 64 * 112) {
        int r = i / 112, c = i - r * 112;
        g_w1h[i] = __float2half(c < 100 ? W1[r * 100 + c] : 0.0f);
    }
    if (i < 112 * 64) {
        int r = i / 64, c = i - r * 64;
        g_w2h[i] = __float2half((r < 100 && c < 50) ? W2[r * 50 + c] : 0.0f);
    }
    if (i < 64 * 32) {
        int r = i / 32, c = i - r * 32;
        g_w3h[i] = __float2half((r < 50 && c < 25) ? W3[r * 25 + c] : 0.0f);
    }
    if (i < 112) g_b1p[i] = (i < 100) ? b1[i] : 0.0f;
    if (i < 64)  g_b2p[i] = (i < 50)  ? b2[i] : 0.0f;
}

// ---------------- CSR fill: store {src, dinv[src]} pairs ----------------
__global__ void k_fill(const void* __restrict__ edge, int E) {
    int e = blockIdx.x * blockDim.x + threadIdx.x;
    if (e >= E) return;
    int s, d;
    if (g_is32) {
        const int* p = (const int*)edge;
        s = p[e]; d = p[E + e];
    } else {
        const long long* p = (const long long*)edge;
        s = (int)p[e]; d = (int)p[E + e];
    }
    float ds = g_dinv[s];
    int pos = atomicAdd(&g_cur[d], 1);
    g_csrw[pos] = make_int2(s, __float_as_int(ds));
}

__device__ __forceinline__ void fma_half8(float* acc, uint4 raw, float w) {
    const __half2* hp = (const __half2*)&raw;
#pragma unroll
    for (int j = 0; j < 4; j++) {
        float2 f = __half22float2(hp[j]);
        acc[2 * j]     = fmaf(f.x, w, acc[2 * j]);
        acc[2 * j + 1] = fmaf(f.y, w, acc[2 * j + 1]);
    }
}

// ---------------- fused agg + wmma GEMM ----------------
// Aggregates 64-wide half input (xh, LD=KP=64) into smem Xs, then Y = [relu](Xs @ W [+bout]).
// BRIN: apply relu(agg + bin) to aggregated input before GEMM.
// 128 threads: gather phase uses 16 groups of 8 (one row each, 4 row-waves);
// mma phase: 4 warps x 16-row tiles.
template <int NP, bool BRIN, bool BROUT>
__global__ void k_gemm_agg(const __half* __restrict__ xh, const __half* __restrict__ W,
                           const float* __restrict__ bin, const float* __restrict__ bout,
                           __half* __restrict__ Yh, int n) {
    constexpr int KP = 64;
    constexpr int ROWS = 64;
    constexpr int NT = NP / 16, KT = KP / 16;
    constexpr int XSP = KP + 8;
    constexpr int NPP = NP + 8;
    constexpr int SM_AB = ROWS * XSP * 2 + KP * NPP * 2;
    constexpr int SM_ST = 4 * 16 * NP * 4;
    constexpr int SM = SM_AB > SM_ST ? SM_AB : SM_ST;
    __shared__ __align__(16) char sm[SM];
    __half* Xs = (__half*)sm;
    __half* Ws = (__half*)(sm + ROWS * XSP * 2);

    int tid = threadIdx.x;
    int wid = tid >> 5;
    int lane = tid & 31;
    int base = blockIdx.x * ROWS;

    // load W [KP x NP] -> Ws (stride NPP)
    for (int i = tid; i < KP * (NP / 8); i += blockDim.x) {
        int r = i / (NP / 8), g = i - r * (NP / 8);
        *(uint4*)(Ws + r * NPP + g * 8) = ((const uint4*)(W + r * NP))[g];
    }

    // gather/aggregate rows into Xs
    int grp = tid >> 3;       // 0..15
    int c = tid & 7;          // feature chunk (8 halves)
    float binr[8];
    if (BRIN) {
        float4 a = *(const float4*)(bin + c * 8);
        float4 b = *(const float4*)(bin + c * 8 + 4);
        binr[0] = a.x; binr[1] = a.y; binr[2] = a.z; binr[3] = a.w;
        binr[4] = b.x; binr[5] = b.y; binr[6] = b.z; binr[7] = b.w;
    }
#pragma unroll
    for (int r0 = 0; r0 < ROWS; r0 += 16) {
        int r = r0 + grp;
        int i = base + r;
        float acc[8] = {0, 0, 0, 0, 0, 0, 0, 0};
        if (i < n) {
            float di = g_dinv[i];
            float s2 = di * di;
            uint4 raw = *(const uint4*)(xh + (size_t)i * KP + c * 8);
            const __half2* hp = (const __half2*)&raw;
#pragma unroll
            for (int j = 0; j < 4; j++) {
                float2 f = __half22float2(hp[j]);
                acc[2 * j]     = f.x * s2;
                acc[2 * j + 1] = f.y * s2;
            }
            int b = g_off[i];
            int e = b + g_degi[i];
            int t = b;
            for (; t + 2 <= e; t += 2) {
                int2 sw0 = g_csrw[t];
                int2 sw1 = g_csrw[t + 1];
                float w0 = __int_as_float(sw0.y) * di;
                float w1 = __int_as_float(sw1.y) * di;
                uint4 v0 = *(const uint4*)(xh + (size_t)sw0.x * KP + c * 8);
                uint4 v1 = *(const uint4*)(xh + (size_t)sw1.x * KP + c * 8);
                fma_half8(acc, v0, w0);
                fma_half8(acc, v1, w1);
            }
            if (t < e) {
                int2 sw0 = g_csrw[t];
                float w0 = __int_as_float(sw0.y) * di;
                uint4 v0 = *(const uint4*)(xh + (size_t)sw0.x * KP + c * 8);
                fma_half8(acc, v0, w0);
            }
            if (BRIN) {
#pragma unroll
                for (int j = 0; j < 8; j++)
                    acc[j] = fmaxf(acc[j] + binr[j], 0.0f);
            }
        }
        __half2 h[4];
#pragma unroll
        for (int j = 0; j < 4; j++)
            h[j] = __float22half2_rn(make_float2(acc[2 * j], acc[2 * j + 1]));
        *(uint4*)(Xs + r * XSP + c * 8) = *(uint4*)h;
    }
    __syncthreads();

    // mma phase
    wmma::fragment<wmma::accumulator, 16, 16, 16, float> cf[NT];
#pragma unroll
    for (int nt = 0; nt < NT; nt++) wmma::fill_fragment(cf[nt], 0.0f);

    int wr = wid * 16;
#pragma unroll
    for (int kt = 0; kt < KT; kt++) {
        wmma::fragment<wmma::matrix_a, 16, 16, 16, __half, wmma::row_major> af;
        wmma::load_matrix_sync(af, Xs + wr * XSP + kt * 16, XSP);
#pragma unroll
        for (int nt = 0; nt < NT; nt++) {
            wmma::fragment<wmma::matrix_b, 16, 16, 16, __half, wmma::row_major> bf;
            wmma::load_matrix_sync(bf, Ws + kt * 16 * NPP + nt * 16, NPP);
            wmma::mma_sync(cf[nt], af, bf, cf[nt]);
        }
    }
    __syncthreads();  // done with Xs/Ws; alias per-warp staging

    float* stg = (float*)sm + wid * 16 * NP;
#pragma unroll
    for (int nt = 0; nt < NT; nt++)
        wmma::store_matrix_sync(stg + nt * 16, cf[nt], NP, wmma::mem_row_major);
    __syncwarp();
    int rbase = base + wr;
    for (int i = lane; i < 16 * (NP / 4); i += 32) {
        int r = i / (NP / 4), cc = i - r * (NP / 4);
        if (rbase + r < n) {
            float4 v = *(const float4*)(stg + r * NP + cc * 4);
            if (BROUT) {
                float4 bb = *(const float4*)(bout + cc * 4);
                v.x = fmaxf(v.x + bb.x, 0.0f); v.y = fmaxf(v.y + bb.y, 0.0f);
                v.z = fmaxf(v.z + bb.z, 0.0f); v.w = fmaxf(v.w + bb.w, 0.0f);
            }
            __half2 h01 = __float22half2_rn(make_float2(v.x, v.y));
            __half2 h23 = __float22half2_rn(make_float2(v.z, v.w));
            uint2 pk = {*(unsigned*)&h01, *(unsigned*)&h23};
            *(uint2*)(Yh + (size_t)(rbase + r) * NP + cc * 4) = pk;
        }
    }
}

// ---------------- wmma GEMM (plain, R13 config) ----------------
template <int KP, int NP, int RT, bool BR>
__global__ void k_gemm_wmma(const __half* __restrict__ X, const __half* __restrict__ W,
                            const float* __restrict__ bias, __half* __restrict__ Yh, int n) {
    constexpr int WARPS = 4;
    constexpr int ROWS = WARPS * RT * 16;
    constexpr int NT = NP / 16, KT = KP / 16;
    constexpr int XSP = KP + 8;
    constexpr int NPP = NP + 8;
    constexpr int SM_AB = ROWS * XSP * 2 + KP * NPP * 2;
    constexpr int SM_ST = WARPS * 16 * NP * 4;
    constexpr int SM = SM_AB > SM_ST ? SM_AB : SM_ST;
    __shared__ __align__(16) char sm[SM];
    __half* Xs = (__half*)sm;
    __half* Ws = (__half*)(sm + ROWS * XSP * 2);

    int tid = threadIdx.x;
    int wid = tid >> 5;
    int lane = tid & 31;
    int base = blockIdx.x * ROWS;

    for (int i = tid; i < KP * (NP / 8); i += blockDim.x) {
        int r = i / (NP / 8), g = i - r * (NP / 8);
        *(uint4*)(Ws + r * NPP + g * 8) = ((const uint4*)(W + r * NP))[g];
    }
    for (int i = tid; i < ROWS * (KP / 8); i += blockDim.x) {
        int r = i / (KP / 8), g = i - r * (KP / 8);
        uint4 v = {0, 0, 0, 0};
        if (base + r < n) v = ((const uint4*)(X + (size_t)(base + r) * KP))[g];
        *(uint4*)(Xs + r * XSP + g * 8) = v;
    }
    __syncthreads();

    wmma::fragment<wmma::accumulator, 16, 16, 16, float> cf[RT][NT];
#pragma unroll
    for (int rt = 0; rt < RT; rt++)
#pragma unroll
        for (int nt = 0; nt < NT; nt++) wmma::fill_fragment(cf[rt][nt], 0.0f);

    int wr = wid * RT * 16;
#pragma unroll
    for (int kt = 0; kt < KT; kt++) {
        wmma::fragment<wmma::matrix_a, 16, 16, 16, __half, wmma::row_major> af[RT];
#pragma unroll
        for (int rt = 0; rt < RT; rt++)
            wmma::load_matrix_sync(af[rt], Xs + (wr + rt * 16) * XSP + kt * 16, XSP);
#pragma unroll
        for (int nt = 0; nt < NT; nt++) {
            wmma::fragment<wmma::matrix_b, 16, 16, 16, __half, wmma::row_major> bf;
            wmma::load_matrix_sync(bf, Ws + kt * 16 * NPP + nt * 16, NPP);
#pragma unroll
            for (int rt = 0; rt < RT; rt++)
                wmma::mma_sync(cf[rt][nt], af[rt], bf, cf[rt][nt]);
        }
    }
    __syncthreads();

    float* stg = (float*)sm + wid * 16 * NP;
#pragma unroll
    for (int rt = 0; rt < RT; rt++) {
#pragma unroll
        for (int nt = 0; nt < NT; nt++)
            wmma::store_matrix_sync(stg + nt * 16, cf[rt][nt], NP, wmma::mem_row_major);
        __syncwarp();
        int rbase = base + wr + rt * 16;
        for (int i = lane; i < 16 * (NP / 4); i += 32) {
            int r = i / (NP / 4), c = i - r * (NP / 4);
            if (rbase + r < n) {
                float4 v = *(const float4*)(stg + r * NP + c * 4);
                if (BR) {
                    float4 bb = *(const float4*)(bias + c * 4);
                    v.x = fmaxf(v.x + bb.x, 0.0f); v.y = fmaxf(v.y + bb.y, 0.0f);
                    v.z = fmaxf(v.z + bb.z, 0.0f); v.w = fmaxf(v.w + bb.w, 0.0f);
                }
                __half2 h01 = __float22half2_rn(make_float2(v.x, v.y));
                __half2 h23 = __float22half2_rn(make_float2(v.z, v.w));
                uint2 pk = {*(unsigned*)&h01, *(unsigned*)&h23};
                *(uint2*)(Yh + (size_t)(rbase + r) * NP + c * 4) = pk;
            }
        }
        __syncwarp();
    }
}

// ---------------- fused agg3 + epilogue MLP: one thread per node ----------------
__global__ void k_agg3_final(const __half* __restrict__ xh, const float* __restrict__ b3,
                             const float* __restrict__ Wl1, const float* __restrict__ bl1,
                             const float* __restrict__ Wl2, const float* __restrict__ bl2,
                             const float* __restrict__ Wl3, const float* __restrict__ bl3,
                             float* __restrict__ out, int n) {
    __shared__ float sW1[25 * 25], sW2[25 * 10], sW3[10];
    __shared__ float sb3[25], sb1[25], sb2[10], sb3l;
    for (int i = threadIdx.x; i < 25 * 25; i += blockDim.x) sW1[i] = Wl1[i];
    for (int i = threadIdx.x; i < 25 * 10; i += blockDim.x) sW2[i] = Wl2[i];
    if (threadIdx.x < 10) sW3[threadIdx.x] = Wl3[threadIdx.x];
    if (threadIdx.x < 25) { sb3[threadIdx.x] = b3[threadIdx.x]; sb1[threadIdx.x] = bl1[threadIdx.x]; }
    if (threadIdx.x < 10) sb2[threadIdx.x] = bl2[threadIdx.x];
    if (threadIdx.x == 0) sb3l = bl3[0];
    __syncthreads();

    int i = blockIdx.x * blockDim.x + threadIdx.x;
    if (i >= n) return;

    float di = g_dinv[i];
    float s2 = di * di;
    float acc[32];
    {
        const uint4* p = (const uint4*)(xh + (size_t)i * 32);
#pragma unroll
        for (int q = 0; q < 4; q++) {
            uint4 raw = p[q];
            const __half2* hp = (const __half2*)&raw;
#pragma unroll
            for (int j = 0; j < 4; j++) {
                float2 f = __half22float2(hp[j]);
                acc[q * 8 + 2 * j]     = f.x * s2;
                acc[q * 8 + 2 * j + 1] = f.y * s2;
            }
        }
    }
    int b = g_off[i];
    int e = b + g_degi[i];
    for (int t = b; t < e; t++) {
        int2 sw = g_csrw[t];
        float w = __int_as_float(sw.y) * di;
        const uint4* p = (const uint4*)(xh + (size_t)sw.x * 32);
        uint4 r0 = p[0], r1 = p[1], r2 = p[2], r3 = p[3];
        fma_half8(acc,      r0, w);
        fma_half8(acc + 8,  r1, w);
        fma_half8(acc + 16, r2, w);
        fma_half8(acc + 24, r3, w);
    }

    float v[25];
#pragma unroll
    for (int f = 0; f < 25; f++)
        v[f] = fmaxf(acc[f] + sb3[f], 0.0f);

    float h1[25];
#pragma unroll
    for (int c = 0; c < 25; c++) {
        float a = sb1[c];
#pragma unroll
        for (int k = 0; k < 25; k++) a = fmaf(v[k], sW1[k * 25 + c], a);
        h1[c] = fmaxf(a, 0.0f);
    }
    float h2[10];
#pragma unroll
    for (int c = 0; c < 10; c++) {
        float a = sb2[c];
#pragma unroll
        for (int k = 0; k < 25; k++) a = fmaf(h1[k], sW2[k * 10 + c], a);
        h2[c] = fmaxf(a, 0.0f);
    }
    float o = sb3l;
#pragma unroll
    for (int k = 0; k < 10; k++) o = fmaf(h2[k], sW3[k], o);
    out[i] = fmaxf(o, 0.0f);
}

// ---------------- launch ----------------
extern "C" void kernel_launch(void* const* d_in, const int* in_sizes, int n_in,
                              void* d_out, int out_size) {
    const float* x   = (const float*)d_in[0];
    const float* W1  = (const float*)d_in[1];
    const float* b1  = (const float*)d_in[2];
    const float* W2  = (const float*)d_in[3];
    const float* b2  = (const float*)d_in[4];
    const float* W3  = (const float*)d_in[5];
    const float* b3  = (const float*)d_in[6];
    const float* Wl1 = (const float*)d_in[7];
    const float* bl1 = (const float*)d_in[8];
    const float* Wl2 = (const float*)d_in[9];
    const float* bl2 = (const float*)d_in[10];
    const float* Wl3 = (const float*)d_in[11];
    const float* bl3 = (const float*)d_in[12];
    const void* edge = d_in[13];
    int E = in_sizes[13] / 2;

    float *b1p, *b2p;
    __half *HX, *H1, *H2, *W1H, *W2H, *W3H;
    cudaGetSymbolAddress((void**)&b1p, g_b1p);
    cudaGetSymbolAddress((void**)&b2p, g_b2p);
    cudaGetSymbolAddress((void**)&HX,  g_hx);
    cudaGetSymbolAddress((void**)&H1,  g_h1);
    cudaGetSymbolAddress((void**)&H2,  g_h2);
    cudaGetSymbolAddress((void**)&W1H, g_w1h);
    cudaGetSymbolAddress((void**)&W2H, g_w2h);
    cudaGetSymbolAddress((void**)&W3H, g_w3h);

    const int T = 256;
    int gN = (NN + T - 1) / T;
    int gE = (E + T - 1) / T;

    // setup + unordered-CSR build
    k_setup<<<(NN * 8 + T - 1) / T, T>>>(x, HX, (const long long*)edge, E);
    k_count<<<gE, T>>>(edge, E);
    k_alloc_padw<<<gN, T>>>(W1, W2, W3, b1, b2);
    k_fill<<<gE, T>>>(edge, E);

    // ----- Layer 1: fused agg(x) + wmma 64->112 (+b1,relu) -----
    k_gemm_agg<112, false, true><<<(NN + 63) / 64, 128>>>(HX, W1H, nullptr, b1p, H2, NN);

    // ----- Layer 2: wmma 112->64 raw, RT=2 -----
    k_gemm_wmma<112, 64, 2, false><<<(NN + 127) / 128, 128>>>(H2, W2H, nullptr, H1, NN);

    // ----- Layer 3: fused agg(t2)+relu(+b2) + wmma 64->32 raw -----
    k_gemm_agg<32, true, false><<<(NN + 63) / 64, 128>>>(H1, W3H, b2p, nullptr, H2, NN);

    // ----- fused agg (32) + MLP epilogue -----
    k_agg3_final<<<gN, T>>>(H2, b3, Wl1, bl1, Wl2, bl2, Wl3, bl3, (float*)d_out, NN);
}

// round 17
// speedup vs baseline: 1.0564x; 1.0276x over previous
#include <cuda_runtime.h>
#include <cuda_fp16.h>
#include <mma.h>
#include <math.h>

using namespace nvcuda;

#define NN 100000
#define EE 1000000

// Scratch (device globals — no allocation allowed)
// NOTE: g_degi is zero-initialized at load and RE-ZEROED at the end of every
// launch by k_agg3_final, so k_setup_count can count into it directly.
__device__ int   g_is32;
__device__ int   g_ctr;
__device__ __align__(8) int2 g_csrw[EE];   // {src, float-bits dinv[src]}
__device__ int   g_degi[NN];
__device__ int   g_off[NN];
__device__ int   g_cur[NN];
__device__ float g_dinv[NN];
__device__ __align__(16) float  g_b1p[112];
__device__ __align__(16) float  g_b2p[64];
__device__ __align__(16) __half g_w1h[64 * 112];
__device__ __align__(16) __half g_w2h[112 * 64];
__device__ __align__(16) __half g_w3h[64 * 32];
__device__ __align__(16) __half g_hx[(size_t)NN * 64];
__device__ __align__(16) __half g_h1[(size_t)NN * 64];
__device__ __align__(16) __half g_h2[(size_t)NN * 112];

// ---------------- setup: dtype detect + x->half + degree count (fused) ----------------
__global__ void k_setup_count(const float* __restrict__ x, __half* __restrict__ xh,
                              const void* __restrict__ edge, int E) {
    __shared__ int s32;
    if (threadIdx.x == 0) s32 = 0;
    __syncthreads();
    // per-block dtype detection (first 256 entries interpreted as int64)
    {
        const long long* e64 = (const long long*)edge;
        if (threadIdx.x < E) {
            long long v = e64[threadIdx.x];
            if (v < 0 || v >= NN) s32 = 1;  // benign smem race (same value)
        }
    }
    __syncthreads();
    bool is32 = (s32 != 0);

    int idx = blockIdx.x * blockDim.x + threadIdx.x;
    if (idx == 0) { g_is32 = is32 ? 1 : 0; g_ctr = 0; }

    if (idx < NN * 8) {
        float4 a = *(const float4*)(x + (size_t)idx * 8);
        float4 b = *(const float4*)(x + (size_t)idx * 8 + 4);
        __half2 h[4];
        h[0] = __float22half2_rn(make_float2(a.x, a.y));
        h[1] = __float22half2_rn(make_float2(a.z, a.w));
        h[2] = __float22half2_rn(make_float2(b.x, b.y));
        h[3] = __float22half2_rn(make_float2(b.z, b.w));
        *(uint4*)(xh + (size_t)idx * 8) = *(uint4*)h;
    }
    if (idx < E) {
        int d = is32 ? ((const int*)edge)[E + idx]
                     : (int)((const long long*)edge)[E + idx];
        atomicAdd(&g_degi[d], 1);  // degi starts at 0 (zeroed by previous launch)
    }
}

// ---------------- segment alloc + dinv + weight/bias pad (merged) ----------------
__global__ void k_alloc_padw(const float* __restrict__ W1, const float* __restrict__ W2,
                             const float* __restrict__ W3, const float* __restrict__ b1,
                             const float* __restrict__ b2) {
    int i = blockIdx.x * blockDim.x + threadIdx.x;
    if (i < NN) {
        int d = g_degi[i];
        g_dinv[i] = rsqrtf((float)d + 1.0f);  // +1 self loop
        int off = atomicAdd(&g_ctr, d);
        g_off[i] = off;
        g_cur[i] = off;
    }
    if (i < 64 * 112) {
        int r = i / 112, c = i - r * 112;
        g_w1h[i] = __float2half(c < 100 ? W1[r * 100 + c] : 0.0f);
    }
    if (i < 112 * 64) {
        int r = i / 64, c = i - r * 64;
        g_w2h[i] = __float2half((r < 100 && c < 50) ? W2[r * 50 + c] : 0.0f);
    }
    if (i < 64 * 32) {
        int r = i / 32, c = i - r * 32;
        g_w3h[i] = __float2half((r < 50 && c < 25) ? W3[r * 25 + c] : 0.0f);
    }
    if (i < 112) g_b1p[i] = (i < 100) ? b1[i] : 0.0f;
    if (i < 64)  g_b2p[i] = (i < 50)  ? b2[i] : 0.0f;
}

// ---------------- CSR fill: store {src, dinv[src]} pairs ----------------
__global__ void k_fill(const void* __restrict__ edge, int E) {
    int e = blockIdx.x * blockDim.x + threadIdx.x;
    if (e >= E) return;
    int s, d;
    if (g_is32) {
        const int* p = (const int*)edge;
        s = p[e]; d = p[E + e];
    } else {
        const long long* p = (const long long*)edge;
        s = (int)p[e]; d = (int)p[E + e];
    }
    float ds = g_dinv[s];
    int pos = atomicAdd(&g_cur[d], 1);
    g_csrw[pos] = make_int2(s, __float_as_int(ds));
}

__device__ __forceinline__ void fma_half8(float* acc, uint4 raw, float w) {
    const __half2* hp = (const __half2*)&raw;
#pragma unroll
    for (int j = 0; j < 4; j++) {
        float2 f = __half22float2(hp[j]);
        acc[2 * j]     = fmaf(f.x, w, acc[2 * j]);
        acc[2 * j + 1] = fmaf(f.y, w, acc[2 * j + 1]);
    }
}

// ---------------- fused agg + wmma GEMM ----------------
template <int NP, bool BRIN, bool BROUT>
__global__ void k_gemm_agg(const __half* __restrict__ xh, const __half* __restrict__ W,
                           const float* __restrict__ bin, const float* __restrict__ bout,
                           __half* __restrict__ Yh, int n) {
    constexpr int KP = 64;
    constexpr int ROWS = 64;
    constexpr int NT = NP / 16, KT = KP / 16;
    constexpr int XSP = KP + 8;
    constexpr int NPP = NP + 8;
    constexpr int SM_AB = ROWS * XSP * 2 + KP * NPP * 2;
    constexpr int SM_ST = 4 * 16 * NP * 4;
    constexpr int SM = SM_AB > SM_ST ? SM_AB : SM_ST;
    __shared__ __align__(16) char sm[SM];
    __half* Xs = (__half*)sm;
    __half* Ws = (__half*)(sm + ROWS * XSP * 2);

    int tid = threadIdx.x;
    int wid = tid >> 5;
    int lane = tid & 31;
    int base = blockIdx.x * ROWS;

    for (int i = tid; i < KP * (NP / 8); i += blockDim.x) {
        int r = i / (NP / 8), g = i - r * (NP / 8);
        *(uint4*)(Ws + r * NPP + g * 8) = ((const uint4*)(W + r * NP))[g];
    }

    int grp = tid >> 3;
    int c = tid & 7;
    float binr[8];
    if (BRIN) {
        float4 a = *(const float4*)(bin + c * 8);
        float4 b = *(const float4*)(bin + c * 8 + 4);
        binr[0] = a.x; binr[1] = a.y; binr[2] = a.z; binr[3] = a.w;
        binr[4] = b.x; binr[5] = b.y; binr[6] = b.z; binr[7] = b.w;
    }
#pragma unroll
    for (int r0 = 0; r0 < ROWS; r0 += 16) {
        int r = r0 + grp;
        int i = base + r;
        float acc[8] = {0, 0, 0, 0, 0, 0, 0, 0};
        if (i < n) {
            float di = g_dinv[i];
            float s2 = di * di;
            uint4 raw = *(const uint4*)(xh + (size_t)i * KP + c * 8);
            const __half2* hp = (const __half2*)&raw;
#pragma unroll
            for (int j = 0; j < 4; j++) {
                float2 f = __half22float2(hp[j]);
                acc[2 * j]     = f.x * s2;
                acc[2 * j + 1] = f.y * s2;
            }
            int b = g_off[i];
            int e = b + g_degi[i];
            int t = b;
            for (; t + 2 <= e; t += 2) {
                int2 sw0 = g_csrw[t];
                int2 sw1 = g_csrw[t + 1];
                float w0 = __int_as_float(sw0.y) * di;
                float w1 = __int_as_float(sw1.y) * di;
                uint4 v0 = *(const uint4*)(xh + (size_t)sw0.x * KP + c * 8);
                uint4 v1 = *(const uint4*)(xh + (size_t)sw1.x * KP + c * 8);
                fma_half8(acc, v0, w0);
                fma_half8(acc, v1, w1);
            }
            if (t < e) {
                int2 sw0 = g_csrw[t];
                float w0 = __int_as_float(sw0.y) * di;
                uint4 v0 = *(const uint4*)(xh + (size_t)sw0.x * KP + c * 8);
                fma_half8(acc, v0, w0);
            }
            if (BRIN) {
#pragma unroll
                for (int j = 0; j < 8; j++)
                    acc[j] = fmaxf(acc[j] + binr[j], 0.0f);
            }
        }
        __half2 h[4];
#pragma unroll
        for (int j = 0; j < 4; j++)
            h[j] = __float22half2_rn(make_float2(acc[2 * j], acc[2 * j + 1]));
        *(uint4*)(Xs + r * XSP + c * 8) = *(uint4*)h;
    }
    __syncthreads();

    wmma::fragment<wmma::accumulator, 16, 16, 16, float> cf[NT];
#pragma unroll
    for (int nt = 0; nt < NT; nt++) wmma::fill_fragment(cf[nt], 0.0f);

    int wr = wid * 16;
#pragma unroll
    for (int kt = 0; kt < KT; kt++) {
        wmma::fragment<wmma::matrix_a, 16, 16, 16, __half, wmma::row_major> af;
        wmma::load_matrix_sync(af, Xs + wr * XSP + kt * 16, XSP);
#pragma unroll
        for (int nt = 0; nt < NT; nt++) {
            wmma::fragment<wmma::matrix_b, 16, 16, 16, __half, wmma::row_major> bf;
            wmma::load_matrix_sync(bf, Ws + kt * 16 * NPP + nt * 16, NPP);
            wmma::mma_sync(cf[nt], af, bf, cf[nt]);
        }
    }
    __syncthreads();

    float* stg = (float*)sm + wid * 16 * NP;
#pragma unroll
    for (int nt = 0; nt < NT; nt++)
        wmma::store_matrix_sync(stg + nt * 16, cf[nt], NP, wmma::mem_row_major);
    __syncwarp();
    int rbase = base + wr;
    for (int i = lane; i < 16 * (NP / 4); i += 32) {
        int r = i / (NP / 4), cc = i - r * (NP / 4);
        if (rbase + r < n) {
            float4 v = *(const float4*)(stg + r * NP + cc * 4);
            if (BROUT) {
                float4 bb = *(const float4*)(bout + cc * 4);
                v.x = fmaxf(v.x + bb.x, 0.0f); v.y = fmaxf(v.y + bb.y, 0.0f);
                v.z = fmaxf(v.z + bb.z, 0.0f); v.w = fmaxf(v.w + bb.w, 0.0f);
            }
            __half2 h01 = __float22half2_rn(make_float2(v.x, v.y));
            __half2 h23 = __float22half2_rn(make_float2(v.z, v.w));
            uint2 pk = {*(unsigned*)&h01, *(unsigned*)&h23};
            *(uint2*)(Yh + (size_t)(rbase + r) * NP + cc * 4) = pk;
        }
    }
}

// ---------------- wmma GEMM (plain) ----------------
template <int KP, int NP, int RT, bool BR>
__global__ void k_gemm_wmma(const __half* __restrict__ X, const __half* __restrict__ W,
                            const float* __restrict__ bias, __half* __restrict__ Yh, int n) {
    constexpr int WARPS = 4;
    constexpr int ROWS = WARPS * RT * 16;
    constexpr int NT = NP / 16, KT = KP / 16;
    constexpr int XSP = KP + 8;
    constexpr int NPP = NP + 8;
    constexpr int SM_AB = ROWS * XSP * 2 + KP * NPP * 2;
    constexpr int SM_ST = WARPS * 16 * NP * 4;
    constexpr int SM = SM_AB > SM_ST ? SM_AB : SM_ST;
    __shared__ __align__(16) char sm[SM];
    __half* Xs = (__half*)sm;
    __half* Ws = (__half*)(sm + ROWS * XSP * 2);

    int tid = threadIdx.x;
    int wid = tid >> 5;
    int lane = tid & 31;
    int base = blockIdx.x * ROWS;

    for (int i = tid; i < KP * (NP / 8); i += blockDim.x) {
        int r = i / (NP / 8), g = i - r * (NP / 8);
        *(uint4*)(Ws + r * NPP + g * 8) = ((const uint4*)(W + r * NP))[g];
    }
    for (int i = tid; i < ROWS * (KP / 8); i += blockDim.x) {
        int r = i / (KP / 8), g = i - r * (KP / 8);
        uint4 v = {0, 0, 0, 0};
        if (base + r < n) v = ((const uint4*)(X + (size_t)(base + r) * KP))[g];
        *(uint4*)(Xs + r * XSP + g * 8) = v;
    }
    __syncthreads();

    wmma::fragment<wmma::accumulator, 16, 16, 16, float> cf[RT][NT];
#pragma unroll
    for (int rt = 0; rt < RT; rt++)
#pragma unroll
        for (int nt = 0; nt < NT; nt++) wmma::fill_fragment(cf[rt][nt], 0.0f);

    int wr = wid * RT * 16;
#pragma unroll
    for (int kt = 0; kt < KT; kt++) {
        wmma::fragment<wmma::matrix_a, 16, 16, 16, __half, wmma::row_major> af[RT];
#pragma unroll
        for (int rt = 0; rt < RT; rt++)
            wmma::load_matrix_sync(af[rt], Xs + (wr + rt * 16) * XSP + kt * 16, XSP);
#pragma unroll
        for (int nt = 0; nt < NT; nt++) {
            wmma::fragment<wmma::matrix_b, 16, 16, 16, __half, wmma::row_major> bf;
            wmma::load_matrix_sync(bf, Ws + kt * 16 * NPP + nt * 16, NPP);
#pragma unroll
            for (int rt = 0; rt < RT; rt++)
                wmma::mma_sync(cf[rt][nt], af[rt], bf, cf[rt][nt]);
        }
    }
    __syncthreads();

    float* stg = (float*)sm + wid * 16 * NP;
#pragma unroll
    for (int rt = 0; rt < RT; rt++) {
#pragma unroll
        for (int nt = 0; nt < NT; nt++)
            wmma::store_matrix_sync(stg + nt * 16, cf[rt][nt], NP, wmma::mem_row_major);
        __syncwarp();
        int rbase = base + wr + rt * 16;
        for (int i = lane; i < 16 * (NP / 4); i += 32) {
            int r = i / (NP / 4), c = i - r * (NP / 4);
            if (rbase + r < n) {
                float4 v = *(const float4*)(stg + r * NP + c * 4);
                if (BR) {
                    float4 bb = *(const float4*)(bias + c * 4);
                    v.x = fmaxf(v.x + bb.x, 0.0f); v.y = fmaxf(v.y + bb.y, 0.0f);
                    v.z = fmaxf(v.z + bb.z, 0.0f); v.w = fmaxf(v.w + bb.w, 0.0f);
                }
                __half2 h01 = __float22half2_rn(make_float2(v.x, v.y));
                __half2 h23 = __float22half2_rn(make_float2(v.z, v.w));
                uint2 pk = {*(unsigned*)&h01, *(unsigned*)&h23};
                *(uint2*)(Yh + (size_t)(rbase + r) * NP + c * 4) = pk;
            }
        }
        __syncwarp();
    }
}

// ---------------- fused agg3 + epilogue MLP + degi reset ----------------
__global__ void k_agg3_final(const __half* __restrict__ xh, const float* __restrict__ b3,
                             const float* __restrict__ Wl1, const float* __restrict__ bl1,
                             const float* __restrict__ Wl2, const float* __restrict__ bl2,
                             const float* __restrict__ Wl3, const float* __restrict__ bl3,
                             float* __restrict__ out, int n) {
    __shared__ float sW1[25 * 25], sW2[25 * 10], sW3[10];
    __shared__ float sb3[25], sb1[25], sb2[10], sb3l;
    for (int i = threadIdx.x; i < 25 * 25; i += blockDim.x) sW1[i] = Wl1[i];
    for (int i = threadIdx.x; i < 25 * 10; i += blockDim.x) sW2[i] = Wl2[i];
    if (threadIdx.x < 10) sW3[threadIdx.x] = Wl3[threadIdx.x];
    if (threadIdx.x < 25) { sb3[threadIdx.x] = b3[threadIdx.x]; sb1[threadIdx.x] = bl1[threadIdx.x]; }
    if (threadIdx.x < 10) sb2[threadIdx.x] = bl2[threadIdx.x];
    if (threadIdx.x == 0) sb3l = bl3[0];
    __syncthreads();

    int i = blockIdx.x * blockDim.x + threadIdx.x;
    if (i >= n) return;

    float di = g_dinv[i];
    float s2 = di * di;
    float acc[32];
    {
        const uint4* p = (const uint4*)(xh + (size_t)i * 32);
#pragma unroll
        for (int q = 0; q < 4; q++) {
            uint4 raw = p[q];
            const __half2* hp = (const __half2*)&raw;
#pragma unroll
            for (int j = 0; j < 4; j++) {
                float2 f = __half22float2(hp[j]);
                acc[q * 8 + 2 * j]     = f.x * s2;
                acc[q * 8 + 2 * j + 1] = f.y * s2;
            }
        }
    }
    int b = g_off[i];
    int e = b + g_degi[i];
    g_degi[i] = 0;  // reset for the NEXT launch's fused count (replay-safe)
    for (int t = b; t < e; t++) {
        int2 sw = g_csrw[t];
        float w = __int_as_float(sw.y) * di;
        const uint4* p = (const uint4*)(xh + (size_t)sw.x * 32);
        uint4 r0 = p[0], r1 = p[1], r2 = p[2], r3 = p[3];
        fma_half8(acc,      r0, w);
        fma_half8(acc + 8,  r1, w);
        fma_half8(acc + 16, r2, w);
        fma_half8(acc + 24, r3, w);
    }

    float v[25];
#pragma unroll
    for (int f = 0; f < 25; f++)
        v[f] = fmaxf(acc[f] + sb3[f], 0.0f);

    float h1[25];
#pragma unroll
    for (int c = 0; c < 25; c++) {
        float a = sb1[c];
#pragma unroll
        for (int k = 0; k < 25; k++) a = fmaf(v[k], sW1[k * 25 + c], a);
        h1[c] = fmaxf(a, 0.0f);
    }
    float h2[10];
#pragma unroll
    for (int c = 0; c < 10; c++) {
        float a = sb2[c];
#pragma unroll
        for (int k = 0; k < 25; k++) a = fmaf(h1[k], sW2[k * 10 + c], a);
        h2[c] = fmaxf(a, 0.0f);
    }
    float o = sb3l;
#pragma unroll
    for (int k = 0; k < 10; k++) o = fmaf(h2[k], sW3[k], o);
    out[i] = fmaxf(o, 0.0f);
}

// ---------------- launch ----------------
extern "C" void kernel_launch(void* const* d_in, const int* in_sizes, int n_in,
                              void* d_out, int out_size) {
    const float* x   = (const float*)d_in[0];
    const float* W1  = (const float*)d_in[1];
    const float* b1  = (const float*)d_in[2];
    const float* W2  = (const float*)d_in[3];
    const float* b2  = (const float*)d_in[4];
    const float* W3  = (const float*)d_in[5];
    const float* b3  = (const float*)d_in[6];
    const float* Wl1 = (const float*)d_in[7];
    const float* bl1 = (const float*)d_in[8];
    const float* Wl2 = (const float*)d_in[9];
    const float* bl2 = (const float*)d_in[10];
    const float* Wl3 = (const float*)d_in[11];
    const float* bl3 = (const float*)d_in[12];
    const void* edge = d_in[13];
    int E = in_sizes[13] / 2;

    float *b1p, *b2p;
    __half *HX, *H1, *H2, *W1H, *W2H, *W3H;
    cudaGetSymbolAddress((void**)&b1p, g_b1p);
    cudaGetSymbolAddress((void**)&b2p, g_b2p);
    cudaGetSymbolAddress((void**)&HX,  g_hx);
    cudaGetSymbolAddress((void**)&H1,  g_h1);
    cudaGetSymbolAddress((void**)&H2,  g_h2);
    cudaGetSymbolAddress((void**)&W1H, g_w1h);
    cudaGetSymbolAddress((void**)&W2H, g_w2h);
    cudaGetSymbolAddress((void**)&W3H, g_w3h);

    const int T = 256;
    int gN = (NN + T - 1) / T;
    int gE = (E + T - 1) / T;
    int gMax = (E > NN * 8 ? E : NN * 8);

    // setup+count (degi pre-zeroed by previous launch) + alloc + fill
    k_setup_count<<<(gMax + T - 1) / T, T>>>(x, HX, edge, E);
    k_alloc_padw<<<gN, T>>>(W1, W2, W3, b1, b2);
    k_fill<<<gE, T>>>(edge, E);

    // ----- Layer 1: fused agg(x) + wmma 64->112 (+b1,relu) -----
    k_gemm_agg<112, false, true><<<(NN + 63) / 64, 128>>>(HX, W1H, nullptr, b1p, H2, NN);

    // ----- Layer 2: wmma 112->64 raw, RT=2 -----
    k_gemm_wmma<112, 64, 2, false><<<(NN + 127) / 128, 128>>>(H2, W2H, nullptr, H1, NN);

    // ----- Layer 3: fused agg(t2)+relu(+b2) + wmma 64->32 raw -----
    k_gemm_agg<32, true, false><<<(NN + 63) / 64, 128>>>(H1, W3H, b2p, nullptr, H2, NN);

    // ----- fused agg (32) + MLP epilogue + degi reset -----
    k_agg3_final<<<gN, T>>>(H2, b3, Wl1, bl1, Wl2, bl2, Wl3, bl3, (float*)d_out, NN);
}